// round 9
// baseline (speedup 1.0000x reference)
#include <cuda_runtime.h>
#include <cstdint>

// Problem constants
#define NB     16
#define NFREQ  513
#define NT     4000
#define NFFT   1024
#define HOP    256
#define OUT_PER_B (3999 * 256)   // 1023744

#define THREADS 256
#define G_HOPS  13               // output hops per block
#define NFRAMES 16               // frames per block (13 + 3 halo)
#define CHUNK   (G_HOPS * HOP)   // 3328 samples per block
#define NCHUNK  ((OUT_PER_B + CHUNK - 1) / CHUNK)   // 308

#define FROW    1058             // frame row stride in floats (1058 % 32 == 2)

// SMEM layout (floats): fbuf 16*1058 | tw 512*float2 | win 1056
#define SM_FBUF 0
#define SM_TW   (SM_FBUF + NFRAMES * FROW)     // 16928
#define SM_WIN  (SM_TW + 1024)                  // 17952
#define SM_FLOATS (SM_WIN + 1056)               // 19008
#define SMEM_BYTES (SM_FLOATS * 4)              // 76032 B -> 3 blocks/SM

// Twiddle table e^{+2*pi*i*j/1024}, j = 0..511
__device__ float2 g_tw[512];

// e^{+2*pi*i*j/32}
__constant__ float W32C[32] = {
     1.000000000f,  0.980785280f,  0.923879533f,  0.831469612f,
     0.707106781f,  0.555570233f,  0.382683432f,  0.195090322f,
     0.000000000f, -0.195090322f, -0.382683432f, -0.555570233f,
    -0.707106781f, -0.831469612f, -0.923879533f, -0.980785280f,
    -1.000000000f, -0.980785280f, -0.923879533f, -0.831469612f,
    -0.707106781f, -0.555570233f, -0.382683432f, -0.195090322f,
     0.000000000f,  0.195090322f,  0.382683432f,  0.555570233f,
     0.707106781f,  0.831469612f,  0.923879533f,  0.980785280f
};
__constant__ float W32S[32] = {
     0.000000000f,  0.195090322f,  0.382683432f,  0.555570233f,
     0.707106781f,  0.831469612f,  0.923879533f,  0.980785280f,
     1.000000000f,  0.980785280f,  0.923879533f,  0.831469612f,
     0.707106781f,  0.555570233f,  0.382683432f,  0.195090322f,
     0.000000000f, -0.195090322f, -0.382683432f, -0.555570233f,
    -0.707106781f, -0.831469612f, -0.923879533f, -0.980785280f,
    -1.000000000f, -0.980785280f, -0.923879533f, -0.831469612f,
    -0.707106781f, -0.555570233f, -0.382683432f, -0.195090322f
};

// bit-reversal tables (4-bit, 3-bit)
__constant__ int BR4[16] = {0,8,4,12,2,10,6,14,1,9,5,13,3,11,7,15};
__constant__ int BR3[8]  = {0,4,2,6,1,5,3,7};

__global__ void tw_init_kernel() {
    int j = blockIdx.x * 256 + threadIdx.x;
    if (j < 512) {
        float s, c;
        sincospif((float)j * (1.0f / 512.0f), &s, &c);   // 2*pi*j/1024
        g_tw[j] = make_float2(c, s);
    }
}

__device__ __forceinline__ float2 cmul(float2 a, float2 b) {
    return make_float2(a.x * b.x - a.y * b.y, a.x * b.y + a.y * b.x);
}

// ---------------------------------------------------------------------------
// In-place 16-pt inverse DIF FFT (radix-2, 4 stages, no temp array).
// Input v[j] natural order; output v[r] = Y[BR4[r]] (bit-reversed).
// Y[m] = sum_j v_in[j] e^{+2*pi*i*j*m/16}
// ---------------------------------------------------------------------------
__device__ __forceinline__ void ifft16_dif(float2 v[16]) {
    // stage 1: L=16, h=8, W16^j = W32[2j]
#pragma unroll
    for (int j = 0; j < 8; j++) {
        float2 u = v[j], t = v[j + 8];
        v[j] = make_float2(u.x + t.x, u.y + t.y);
        float dx = u.x - t.x, dy = u.y - t.y;
        float wc = W32C[2 * j], ws = W32S[2 * j];
        v[j + 8] = make_float2(dx * wc - dy * ws, dx * ws + dy * wc);
    }
    // stage 2: L=8, h=4, W8^j = W32[4j]
#pragma unroll
    for (int g = 0; g < 16; g += 8) {
#pragma unroll
        for (int j = 0; j < 4; j++) {
            float2 u = v[g + j], t = v[g + j + 4];
            v[g + j] = make_float2(u.x + t.x, u.y + t.y);
            float dx = u.x - t.x, dy = u.y - t.y;
            float wc = W32C[4 * j], ws = W32S[4 * j];
            v[g + j + 4] = make_float2(dx * wc - dy * ws, dx * ws + dy * wc);
        }
    }
    // stage 3: L=4, h=2, W4^0=1, W4^1=+i  (multiply by i: (x,y)->(-y,x))
#pragma unroll
    for (int g = 0; g < 16; g += 4) {
        {
            float2 u = v[g], t = v[g + 2];
            v[g]     = make_float2(u.x + t.x, u.y + t.y);
            v[g + 2] = make_float2(u.x - t.x, u.y - t.y);
        }
        {
            float2 u = v[g + 1], t = v[g + 3];
            v[g + 1] = make_float2(u.x + t.x, u.y + t.y);
            float dx = u.x - t.x, dy = u.y - t.y;
            v[g + 3] = make_float2(-dy, dx);
        }
    }
    // stage 4: L=2, h=1
#pragma unroll
    for (int g = 0; g < 16; g += 2) {
        float2 u = v[g], t = v[g + 1];
        v[g]     = make_float2(u.x + t.x, u.y + t.y);
        v[g + 1] = make_float2(u.x - t.x, u.y - t.y);
    }
}

// ---------------------------------------------------------------------------
// Fused kernel: stage spectra into fbuf rows, in-row FFT, OLA + normalize.
// grid = (NCHUNK, NB), block = 256 (8 warps), 3 blocks/SM.
// ---------------------------------------------------------------------------
__global__ void __launch_bounds__(THREADS, 3)
istft_fused_kernel(const float* __restrict__ mag,
                   const float* __restrict__ cosp,
                   const float* __restrict__ sinp,
                   const float* __restrict__ window,
                   float* __restrict__ out) {
    extern __shared__ float smem[];
    float*  fbuf  = smem + SM_FBUF;
    float2* tw    = reinterpret_cast<float2*>(smem + SM_TW);
    float*  win_s = smem + SM_WIN;

    const int tid  = threadIdx.x;
    const int w    = tid >> 5;
    const int lane = tid & 31;
    const int c    = blockIdx.x;
    const int b    = blockIdx.y;
    const int ft0  = G_HOPS * c - 1;                 // first frame slot's t

    // tables
    for (int j = tid; j < 512; j += THREADS) tw[j] = g_tw[j];
    for (int j = tid; j < 1024; j += THREADS) win_s[j + (j >> 5)] = window[j];

    // ---- stage all 16 spectra into fbuf rows ----
    {
        const int t_off = tid & 15;                  // frame slot
        const int f_off = tid >> 4;                  // 0..15
        const int t = ft0 + t_off;
        if (t >= 0 && t < NT) {
            float2* Sld = reinterpret_cast<float2*>(fbuf + t_off * FROW);
            const size_t base = (size_t)b * NFREQ * NT + (size_t)t;
            for (int f = f_off; f < NFREQ; f += 16) {
                size_t idx = base + (size_t)f * NT;
                float m  = mag[idx];
                float cp = cosp[idx];
                float sn = sinp[idx];
                Sld[f] = make_float2(m * cp, m * sn);
            }
        }
    }
    __syncthreads();

    const float inv_n = 1.0f / 1024.0f;
    const int n1 = __brev(lane) >> 27;               // bitrev5(lane)

    // ---- each warp FFTs 2 frame rows in place ----
#pragma unroll 1
    for (int slot = w; slot < NFRAMES; slot += 8) {
        const int t = ft0 + slot;
        if (t < 0 || t >= NT) continue;
        float* frow = fbuf + slot * FROW;
        const float2* H = reinterpret_cast<const float2*>(frow);

        // Z[k] = (H[k]+conj(H[512-k])) + i*W1024^k*(H[k]-conj(H[512-k]))
        float2 v[16];
#pragma unroll
        for (int k2 = 0; k2 < 16; k2++) {
            const int k = lane + (k2 << 5);          // 0..511
            float2 a  = H[k];
            float2 bb = H[512 - k];
            float2 W;
            if (k == 0) { a.y = 0.0f; bb.y = 0.0f; W = make_float2(1.0f, 0.0f); }
            else        { W = tw[k]; }
            float qx = a.x - bb.x;
            float qy = a.y + bb.y;
            v[k2].x = (a.x + bb.x) - (W.x * qy + W.y * qx);
            v[k2].y = (a.y - bb.y) + (W.x * qx - W.y * qy);
        }

        ifft16_dif(v);                               // v[r] = Y[BR4[r]]

        // mid twiddle e^{2*pi*i*n2*lane/512}, applied in n2 order to reg BR4[n2]
        {
            float2 Wb = tw[2 * lane];
            float2 Wc = Wb;
#pragma unroll
            for (int n2 = 1; n2 < 16; n2++) {
                const int r = BR4[n2];
                v[r] = cmul(v[r], Wc);
                if (n2 < 15) Wc = cmul(Wc, Wb);
            }
        }

        // cross-lane 32-pt inverse DIF over lanes (order-agnostic per reg)
#pragma unroll
        for (int s = 0; s < 5; s++) {
            const int h = 16 >> s;
            const float wc = W32C[(lane & (h - 1)) << s];
            const float ws = W32S[(lane & (h - 1)) << s];
            const bool hi = (lane & h) != 0;
#pragma unroll
            for (int r = 0; r < 16; r++) {
                float px = __shfl_xor_sync(0xffffffffu, v[r].x, h);
                float py = __shfl_xor_sync(0xffffffffu, v[r].y, h);
                float2 rr;
                if (hi) {
                    float dx = px - v[r].x;
                    float dy = py - v[r].y;
                    rr = make_float2(dx * wc - dy * ws, dx * ws + dy * wc);
                } else {
                    rr = make_float2(v[r].x + px, v[r].y + py);
                }
                v[r] = rr;
            }
        }

        // windowed store: lane owns samples n = 32*n1 + {4q..4q+3}
        // sample 4q,4q+1 <- reg BR3[q] (n2=2q); 4q+2,4q+3 <- reg BR3[q]+8 (n2=2q+1)
        const int bidx = 33 * n1;                    // skew(32*n1)
#pragma unroll
        for (int q = 0; q < 8; q++) {
            const int rA = BR3[q];
            const int rB = rA + 8;
            const int i0 = bidx + 4 * q;
            frow[i0 + 0] = v[rA].x * win_s[i0 + 0] * inv_n;
            frow[i0 + 1] = v[rA].y * win_s[i0 + 1] * inv_n;
            frow[i0 + 2] = v[rB].x * win_s[i0 + 2] * inv_n;
            frow[i0 + 3] = v[rB].y * win_s[i0 + 3] * inv_n;
        }
    }
    __syncthreads();

    // ---- overlap-add + envelope normalize + trim ----
    const int j0 = c * CHUNK;
    float* outb = out + (size_t)b * OUT_PER_B;
#pragma unroll 1
    for (int i = 0; i < G_HOPS; i++) {
        const int j = j0 + i * HOP + tid;
        if (j >= OUT_PER_B) break;
        const int s = j + NFFT / 2;
        int thi = s >> 8; if (thi > NT - 1) thi = NT - 1;
        int tlo = (s - 768) >> 8; if (tlo < 0) tlo = 0;

        float acc = 0.0f, env = 0.0f;
#pragma unroll 4
        for (int t = tlo; t <= thi; t++) {
            const int n  = s - (t << 8);             // [0,1023]
            const int ni = n + (n >> 5);
            acc += fbuf[(t - ft0) * FROW + ni];
            float wv = win_s[ni];
            env += wv * wv;
        }
        outb[j] = acc / (env + 1e-11f);
    }
}

// ---------------------------------------------------------------------------
extern "C" void kernel_launch(void* const* d_in, const int* in_sizes, int n_in,
                              void* d_out, int out_size) {
    const float* mag    = (const float*)d_in[0];
    const float* cosp   = (const float*)d_in[1];
    const float* sinp   = (const float*)d_in[2];
    const float* window = (const float*)d_in[3];
    float* out = (float*)d_out;

    cudaFuncSetAttribute(istft_fused_kernel,
                         cudaFuncAttributeMaxDynamicSharedMemorySize, SMEM_BYTES);

    tw_init_kernel<<<2, 256>>>();

    dim3 grid(NCHUNK, NB);   // 308 x 16
    istft_fused_kernel<<<grid, THREADS, SMEM_BYTES>>>(mag, cosp, sinp, window, out);
}

// round 13
// speedup vs baseline: 1.7541x; 1.7541x over previous
#include <cuda_runtime.h>
#include <cstdint>

// Problem constants
#define NB     16
#define NFREQ  513
#define NT     4000
#define NFFT   1024
#define HOP    256
#define OUT_PER_B (3999 * 256)   // 1023744

#define THREADS 256
#define G_HOPS  13               // output hops per block
#define NFRAMES 16               // frames per block (13 + 3 halo)
#define CHUNK   (G_HOPS * HOP)   // 3328
#define NCHUNK  ((OUT_PER_B + CHUNK - 1) / CHUNK)   // 308

#define FROW    1056             // frame row stride (floats)
#define ZBLK    36               // words per 16-complex block (conflict-free LDS.128)
#define ZFRAME  1156             // words per staged frame (even)

// parity-preserving skew: +2 floats per 64-float block (keeps float2 alignment)
#define SKEW(n) ((n) + (((n) >> 6) << 1))

// SMEM layout (floats)
#define SM_FBUF 0
#define SM_ZST  (SM_FBUF + NFRAMES * FROW)          // 16896
#define SM_TW   (SM_ZST + 8 * ZFRAME)               // 26144
#define SM_WIN  (SM_TW + 1024)                      // 27168
#define SM_IENV (SM_WIN + 1056)                     // 28224
#define SM_FLOATS (SM_IENV + 256)                   // 28480
#define SMEM_BYTES (SM_FLOATS * 4)                  // 113920 B -> 2 blocks/SM

// Twiddle table e^{+2*pi*i*j/1024}, j = 0..511
__device__ float2 g_tw[512];

// e^{+2*pi*i*j/32}
__constant__ float W32C[32] = {
     1.000000000f,  0.980785280f,  0.923879533f,  0.831469612f,
     0.707106781f,  0.555570233f,  0.382683432f,  0.195090322f,
     0.000000000f, -0.195090322f, -0.382683432f, -0.555570233f,
    -0.707106781f, -0.831469612f, -0.923879533f, -0.980785280f,
    -1.000000000f, -0.980785280f, -0.923879533f, -0.831469612f,
    -0.707106781f, -0.555570233f, -0.382683432f, -0.195090322f,
     0.000000000f,  0.195090322f,  0.382683432f,  0.555570233f,
     0.707106781f,  0.831469612f,  0.923879533f,  0.980785280f
};
__constant__ float W32S[32] = {
     0.000000000f,  0.195090322f,  0.382683432f,  0.555570233f,
     0.707106781f,  0.831469612f,  0.923879533f,  0.980785280f,
     1.000000000f,  0.980785280f,  0.923879533f,  0.831469612f,
     0.707106781f,  0.555570233f,  0.382683432f,  0.195090322f,
     0.000000000f, -0.195090322f, -0.382683432f, -0.555570233f,
    -0.707106781f, -0.831469612f, -0.923879533f, -0.980785280f,
    -1.000000000f, -0.980785280f, -0.923879533f, -0.831469612f,
    -0.707106781f, -0.555570233f, -0.382683432f, -0.195090322f
};

__global__ void tw_init_kernel() {
    int j = blockIdx.x * 256 + threadIdx.x;
    if (j < 512) {
        float s, c;
        sincospif((float)j * (1.0f / 512.0f), &s, &c);   // 2*pi*j/1024
        g_tw[j] = make_float2(c, s);
    }
}

__device__ __forceinline__ float2 cmul(float2 a, float2 b) {
    return make_float2(a.x * b.x - a.y * b.y, a.x * b.y + a.y * b.x);
}

// ---------------------------------------------------------------------------
// 16-point inverse DFT in registers (radix-4 x radix-4), natural in/out.
// ---------------------------------------------------------------------------
__device__ __forceinline__ void ifft16(float2 v[16]) {
    float2 g[16];
#pragma unroll
    for (int j1 = 0; j1 < 4; j1++) {
        float2 a = v[j1], b = v[j1 + 4], c = v[j1 + 8], d = v[j1 + 12];
        float t0x = a.x + c.x, t0y = a.y + c.y;
        float t1x = a.x - c.x, t1y = a.y - c.y;
        float t2x = b.x + d.x, t2y = b.y + d.y;
        float t3x = b.x - d.x, t3y = b.y - d.y;
        g[j1 * 4 + 0] = make_float2(t0x + t2x, t0y + t2y);
        g[j1 * 4 + 1] = make_float2(t1x - t3y, t1y + t3x);
        g[j1 * 4 + 2] = make_float2(t0x - t2x, t0y - t2y);
        g[j1 * 4 + 3] = make_float2(t1x + t3y, t1y - t3x);
    }
#pragma unroll
    for (int j1 = 1; j1 < 4; j1++) {
#pragma unroll
        for (int m2 = 1; m2 < 4; m2++) {
            float wc = W32C[2 * j1 * m2];
            float ws = W32S[2 * j1 * m2];
            float2 x = g[j1 * 4 + m2];
            g[j1 * 4 + m2] = make_float2(x.x * wc - x.y * ws, x.x * ws + x.y * wc);
        }
    }
#pragma unroll
    for (int m2 = 0; m2 < 4; m2++) {
        float2 a = g[m2], b = g[4 + m2], c = g[8 + m2], d = g[12 + m2];
        float t0x = a.x + c.x, t0y = a.y + c.y;
        float t1x = a.x - c.x, t1y = a.y - c.y;
        float t2x = b.x + d.x, t2y = b.y + d.y;
        float t3x = b.x - d.x, t3y = b.y - d.y;
        v[m2 + 0]  = make_float2(t0x + t2x, t0y + t2y);
        v[m2 + 4]  = make_float2(t1x - t3y, t1y + t3x);
        v[m2 + 8]  = make_float2(t0x - t2x, t0y - t2y);
        v[m2 + 12] = make_float2(t1x + t3y, t1y - t3x);
    }
}

// ---------------------------------------------------------------------------
// Fused kernel. grid = (NCHUNK, NB), block = 256 (8 warps), 2 blocks/SM.
// ---------------------------------------------------------------------------
__global__ void __launch_bounds__(THREADS, 2)
istft_fused_kernel(const float* __restrict__ mag,
                   const float* __restrict__ cosp,
                   const float* __restrict__ sinp,
                   const float* __restrict__ window,
                   float* __restrict__ out) {
    extern __shared__ float smem[];
    float*  fbuf  = smem + SM_FBUF;
    float*  zst   = smem + SM_ZST;
    float2* tw    = reinterpret_cast<float2*>(smem + SM_TW);
    float*  win_s = smem + SM_WIN;
    float*  ienv  = smem + SM_IENV;

    const int tid  = threadIdx.x;
    const int w    = tid >> 5;
    const int lane = tid & 31;
    const int c    = blockIdx.x;
    const int b    = blockIdx.y;
    const int ft0  = G_HOPS * c - 1;

    // ---- tables ----
    for (int j = tid; j < 512; j += THREADS) tw[j] = g_tw[j];
    for (int j = tid; j < 1024; j += THREADS)
        win_s[SKEW(j)] = window[j] * (1.0f / 1024.0f);
    {   // interior inverse envelope: env(s) depends only on s mod 256
        float e = 0.0f;
#pragma unroll
        for (int q = 0; q < 4; q++) {
            float wv = window[tid + 256 * q];
            e += wv * wv;
        }
        ienv[tid] = 1.0f / (e + 1e-11f);
    }
    __syncthreads();

    const size_t bbase = (size_t)b * NFREQ * NT;
    const int n1 = __brev(lane) >> 27;               // bitrev5(lane)

    // ---- two rounds: stage 8 Z-spectra, FFT 8 frames ----
#pragma unroll 1
    for (int r = 0; r < 2; r++) {
        // stage: thread handles conjugate pair (k, 512-k) for one frame
        {
            const int t_off = tid & 7;
            const int f_off = tid >> 3;              // 0..31
            const int t = ft0 + r * 8 + t_off;
            if (t >= 0 && t < NT) {
                float* zb = zst + t_off * ZFRAME;
                const size_t base = bbase + (size_t)t;
#pragma unroll 1
                for (int k = f_off; k <= 256; k += 32) {
                    const int km = 512 - k;
                    size_t ia = base + (size_t)k * NT;
                    size_t ib = base + (size_t)km * NT;
                    float ma = mag[ia],  ca = cosp[ia], sa = sinp[ia];
                    float mb = mag[ib],  cb = cosp[ib], sb = sinp[ib];
                    float ax = ma * ca, ay = ma * sa;
                    float bx = mb * cb, by = mb * sb;
                    if (k == 0) { ay = 0.0f; by = 0.0f; }
                    float2 W = tw[k];
                    float qx = ax - bx, qy = ay + by;
                    float S = ax + bx, D = ay - by;
                    float T = W.x * qy + W.y * qx;
                    float U = W.x * qx - W.y * qy;
                    // Z[k]
                    {
                        int a0 = ZBLK * (k >> 4) + 2 * (k & 15);
                        *reinterpret_cast<float2*>(zb + a0) = make_float2(S - T, D + U);
                    }
                    // Z[512-k]
                    if (k > 0 && k < 256) {
                        int a1 = ZBLK * (km >> 4) + 2 * (km & 15);
                        *reinterpret_cast<float2*>(zb + a1) = make_float2(S + T, U - D);
                    }
                }
            }
        }
        __syncthreads();

        // FFT: warp w handles staged frame w
        const int slot = r * 8 + w;
        const int t = ft0 + slot;
        if (t >= 0 && t < NT) {
            // load 16 contiguous complex per lane: k = 16*lane + k2
            float2 v[16];
            {
                const float4* zr = reinterpret_cast<const float4*>(zst + w * ZFRAME + ZBLK * lane);
#pragma unroll
                for (int j = 0; j < 8; j++) {
                    float4 q = zr[j];
                    v[2 * j]     = make_float2(q.x, q.y);
                    v[2 * j + 1] = make_float2(q.z, q.w);
                }
            }

            // cross-lane 32-pt inverse DIF over k1 = lane; output lane holds n1
#pragma unroll
            for (int s = 0; s < 5; s++) {
                const int h = 16 >> s;
                const float wc = W32C[(lane & (h - 1)) << s];
                const float ws = W32S[(lane & (h - 1)) << s];
                const bool hi = (lane & h) != 0;
#pragma unroll
                for (int k2 = 0; k2 < 16; k2++) {
                    float px = __shfl_xor_sync(0xffffffffu, v[k2].x, h);
                    float py = __shfl_xor_sync(0xffffffffu, v[k2].y, h);
                    float2 rr;
                    if (hi) {
                        float dx = px - v[k2].x;
                        float dy = py - v[k2].y;
                        rr = make_float2(dx * wc - dy * ws, dx * ws + dy * wc);
                    } else {
                        rr = make_float2(v[k2].x + px, v[k2].y + py);
                    }
                    v[k2] = rr;
                }
            }

            // mid twiddle: v[k2] *= W512^{k2*n1} via power recurrence
            {
                float2 Wb = tw[2 * n1];
                float2 Wc = Wb;
#pragma unroll
                for (int k2 = 1; k2 < 16; k2++) {
                    v[k2] = cmul(v[k2], Wc);
                    Wc = cmul(Wc, Wb);
                }
            }

            // 16-pt register IDFT over k2 -> n2 (natural order)
            ifft16(v);

            // windowed store: lane n1 owns samples n = 2*n1 + 64*n2 (+1)
            float* frow = fbuf + slot * FROW;
#pragma unroll
            for (int n2 = 0; n2 < 16; n2++) {
                const int n  = 2 * n1 + (n2 << 6);
                const int ni = SKEW(n);              // = n + 2*n2, even
                float2 wv = *reinterpret_cast<const float2*>(win_s + ni);
                *reinterpret_cast<float2*>(frow + ni) =
                    make_float2(v[n2].x * wv.x, v[n2].y * wv.y);
            }
        }
        __syncthreads();
    }

    // ---- overlap-add + normalize + trim ----
    const int j0 = c * CHUNK;
    float* outb = out + (size_t)b * OUT_PER_B;

    if (c > 0 && c < NCHUNK - 1) {
        // interior: exactly 4 frames per sample, env from table; 2 samples/thread
#pragma unroll 1
        for (int i = 0; i < 7; i++) {
            const int p = i * 256 + tid;
            if (p >= CHUNK / 2) break;
            const int j = j0 + 2 * p;
            const int s = j + NFFT / 2;
            const int t0 = (s - 768) >> 8;
            const int r0 = t0 - ft0;
            const int nb = s - (t0 << 8);            // [768,1022], even
            float2 acc = make_float2(0.0f, 0.0f);
#pragma unroll
            for (int q = 0; q < 4; q++) {
                const int n  = nb - (q << 8);
                const int ni = SKEW(n);              // even
                float2 f = *reinterpret_cast<const float2*>(fbuf + (r0 + q) * FROW + ni);
                acc.x += f.x; acc.y += f.y;
            }
            const int m = s & 255;                   // even
            float2 o = make_float2(acc.x * ienv[m], acc.y * ienv[m + 1]);
            *reinterpret_cast<float2*>(outb + j) = o;
        }
    } else {
        // edge blocks: honest env accumulation (win_s is w/1024 -> scale env)
#pragma unroll 1
        for (int i = 0; i < G_HOPS; i++) {
            const int j = j0 + i * HOP + tid;
            if (j >= OUT_PER_B) break;
            const int s = j + NFFT / 2;
            int thi = s >> 8; if (thi > NT - 1) thi = NT - 1;
            int tlo = (s - 768) >> 8; if (tlo < 0) tlo = 0;
            float acc = 0.0f, env = 0.0f;
#pragma unroll 4
            for (int t = tlo; t <= thi; t++) {
                const int n  = s - (t << 8);
                const int ni = SKEW(n);
                acc += fbuf[(t - ft0) * FROW + ni];
                float wv = win_s[ni];
                env += wv * wv;
            }
            outb[j] = acc / (env * 1048576.0f + 1e-11f);
        }
    }
}

// ---------------------------------------------------------------------------
extern "C" void kernel_launch(void* const* d_in, const int* in_sizes, int n_in,
                              void* d_out, int out_size) {
    const float* mag    = (const float*)d_in[0];
    const float* cosp   = (const float*)d_in[1];
    const float* sinp   = (const float*)d_in[2];
    const float* window = (const float*)d_in[3];
    float* out = (float*)d_out;

    cudaFuncSetAttribute(istft_fused_kernel,
                         cudaFuncAttributeMaxDynamicSharedMemorySize, SMEM_BYTES);

    tw_init_kernel<<<2, 256>>>();

    dim3 grid(NCHUNK, NB);   // 308 x 16
    istft_fused_kernel<<<grid, THREADS, SMEM_BYTES>>>(mag, cosp, sinp, window, out);
}